// round 8
// baseline (speedup 1.0000x reference)
#include <cuda_runtime.h>
#include <cstdint>
#include <cstddef>

#define T_STEPS 4096
#define IN_DIM  128
#define HIDDEN  2048
#define LEAK    0.9f
#define NCTA    128
#define TPB     512
#define ROWS_PER_CTA 16   // HIDDEN / NCTA

// ---------------- device scratch (static: no allocations allowed) ----------------
__device__ float g_inp[(size_t)T_STEPS * HIDDEN];   // precomputed input projection [T,H]

// One 128B line per (parity, producer CTA): 16 act values + step tag.
struct __align__(128) ActLine {
    float act[16];
    unsigned int tag;
    unsigned int pad[15];
};
__device__ ActLine g_lines[2][NCTA];                // 32 KB, L2-resident

// ---------------- packed fp32x2 helpers ----------------
__device__ __forceinline__ unsigned long long pack2(float lo, float hi) {
    unsigned long long u;
    asm("mov.b64 %0, {%1, %2};" : "=l"(u) : "f"(lo), "f"(hi));
    return u;
}
__device__ __forceinline__ void unpack2(unsigned long long u, float& lo, float& hi) {
    asm("mov.b64 {%0, %1}, %2;" : "=f"(lo), "=f"(hi) : "l"(u));
}
__device__ __forceinline__ unsigned long long ffma2(unsigned long long a,
                                                    unsigned long long b,
                                                    unsigned long long c) {
    unsigned long long d;
    asm("fma.rn.f32x2 %0, %1, %2, %3;" : "=l"(d) : "l"(a), "l"(b), "l"(c));
    return d;
}

// ---------------- sync primitives ----------------
// Producer: release store (orders the warp's prior act stores at L2).
__device__ __forceinline__ void st_release_u32(unsigned int* p, unsigned int v) {
    asm volatile("st.release.gpu.global.u32 [%0], %1;" :: "l"(p), "r"(v) : "memory");
}
// Consumer: WEAK volatile poll — one load per attempt, pipelines freely.
__device__ __forceinline__ unsigned int ld_poll_u32(const unsigned int* p) {
    unsigned int v;
    asm volatile("ld.volatile.global.u32 %0, [%1];" : "=r"(v) : "l"(p) : "memory");
    return v;
}

// ---------------- phase A: inp_proj[t][h] = input[t,:] . w_ih[h,:] + b_ih[h] ----------------
__global__ void inp_proj_kernel(const float* __restrict__ input,
                                const float* __restrict__ w_ih,
                                const float* __restrict__ b_ih) {
    __shared__ float s_in[16 * IN_DIM];
    const int tblk = blockIdx.x;
    const int tid  = threadIdx.x;

    for (int i = tid; i < 16 * IN_DIM; i += 256)
        s_in[i] = input[(size_t)tblk * 16 * IN_DIM + i];
    __syncthreads();

    const float4* s_in4 = reinterpret_cast<const float4*>(s_in);

    for (int j = 0; j < 8; j++) {
        const int h = tid + 256 * j;
        float acc[16];
        const float b = b_ih[h];
#pragma unroll
        for (int t = 0; t < 16; t++) acc[t] = b;

        const float4* wrow = reinterpret_cast<const float4*>(w_ih + (size_t)h * IN_DIM);
#pragma unroll 4
        for (int kc = 0; kc < IN_DIM / 4; kc++) {
            const float4 w4 = wrow[kc];
#pragma unroll
            for (int t = 0; t < 16; t++) {
                const float4 iv = s_in4[t * (IN_DIM / 4) + kc];  // warp-broadcast
                acc[t] += w4.x * iv.x + w4.y * iv.y + w4.z * iv.z + w4.w * iv.w;
            }
        }
#pragma unroll
        for (int t = 0; t < 16; t++)
            g_inp[(size_t)(tblk * 16 + t) * HIDDEN + h] = acc[t];
    }
}

// ---------------- phase B: persistent recurrence kernel ----------------
// 128 CTAs x 512 threads. CTA b owns rows [16b, 16b+16); thread tid owns all
// 16 rows x cols [4*tid, 4*tid+4) (64 weights in regs).
// Sync: producer warp 0 publishes 16 acts + tag in ONE 128B line
// (weak stores + st.release tag). Each consumer THREAD weak-polls only its
// own source CTA's tag (1 load/attempt), then reads the act float4 from the
// SAME line with a tag-data-dependent address (ordering without acquire).
// No grid barrier, no atomics, no fences. Replay-safe via per-parity bases.
__global__ void __launch_bounds__(TPB, 1)
reservoir_kernel(const float* __restrict__ w_hh,
                 float* __restrict__ out_act,
                 float* __restrict__ out_hid) {
    __shared__ float s_part[2][ROWS_PER_CTA][17];   // parity double-buffered
    __shared__ unsigned int s_base[2];              // per-parity tag base

    const int tid  = threadIdx.x;
    const int lane = tid & 31;
    const int w    = tid >> 5;                   // warp id 0..15
    const int cta  = blockIdx.x;
    const int base_row = cta * ROWS_PER_CTA;

    // Per-parity tag bases from OWN lines (sole writer = own warp 0, which
    // hasn't written yet). Identical across CTAs (same launch history).
    if (tid == 0) {
        s_base[0] = ld_poll_u32(&g_lines[0][cta].tag);
        s_base[1] = ld_poll_u32(&g_lines[1][cta].tag);
    }

    // Load weights: W[r] = cols [4*tid, 4*tid+4) of row base_row + r.
    unsigned long long W[ROWS_PER_CTA][2];
#pragma unroll
    for (int r = 0; r < ROWS_PER_CTA; r++) {
        const float4 wv = reinterpret_cast<const float4*>(
            w_hh + (size_t)(base_row + r) * HIDDEN)[tid];
        W[r][0] = pack2(wv.x, wv.y);
        W[r][1] = pack2(wv.z, wv.w);
    }
    __syncthreads();
    const unsigned int B0 = s_base[0];
    const unsigned int B1 = s_base[1];

    const int fin_row = base_row + lane;   // finalize row (lanes<16 of warps 0,2)
    float hid = 0.0f;                      // identical copies in warps 0 and 2

    // ---- t = 0 peeled: previous act is the zero vector -> dot = 0 ----
    // Publish tag = B0 + 1 into parity-0 line.
    if (lane < ROWS_PER_CTA && (w == 0 || w == 2)) {
        const float u0 = g_inp[fin_row];
        const float nh = LEAK * u0;
        const float na = tanhf(nh);
        hid = nh;
        if (w == 0) {
            g_lines[0][cta].act[lane] = na;
            __syncwarp(0x0000ffffu);
            if (lane == 0) st_release_u32(&g_lines[0][cta].tag, B0 + 1u);
        } else {
            out_act[fin_row] = na;
            out_hid[fin_row] = nh;
        }
    }

    const int src_cta = tid >> 2;          // source CTA for this thread's 4 cols
    const int src_off = tid & 3;           // float4 index within the line

    for (int t = 1; t < T_STEPS; t++) {
        // prefetch u_t (warps 0 and 2 only; issued before the wait)
        float u = 0.0f;
        if (lane < ROWS_PER_CTA && (w == 0 || w == 2))
            u = g_inp[(size_t)t * HIDDEN + fin_row];

        // ---- per-thread weak poll of source tag (parity (t+1)&1) ----
        // Publish at step s set tag = B_{s&1} + s + 1; source step is t-1,
        // parity (t-1)&1 == (t+1)&1, so target = B_{(t+1)&1} + t.
        const ActLine* src = &g_lines[(t + 1) & 1][src_cta];
        const unsigned int tgt = ((t & 1) ? B0 : B1) + (unsigned int)t;
        unsigned int tg;
        do { tg = ld_poll_u32(&src->tag); } while ((int)(tg - tgt) < 0);

        // act float4 from the SAME (hot) line; address depends on tg so the
        // read is performed after the tag value returned. (tg - tgt) >> 31
        // == 0 on loop exit, wrap-safe.
        const float4 a = __ldcg(reinterpret_cast<const float4*>(src->act)
                                + src_off + ((tg - tgt) >> 31));
        const unsigned long long A0 = pack2(a.x, a.y);
        const unsigned long long A1 = pack2(a.z, a.w);

        // ---- 16 independent 2-deep FFMA2 chains ----
        float v[ROWS_PER_CTA];
#pragma unroll
        for (int r = 0; r < ROWS_PER_CTA; r++) {
            unsigned long long P = ffma2(W[r][0], A0, 0ull);
            P = ffma2(W[r][1], A1, P);
            float lo, hi; unpack2(P, lo, hi);
            v[r] = lo + hi;
        }

        // ---- value-splitting warp butterfly: 16 values -> 1 per lane ----
        {
            const bool up = (lane & 16) != 0;
#pragma unroll
            for (int i = 0; i < 8; i++) {
                const float send = up ? v[i] : v[i + 8];
                const float recv = __shfl_xor_sync(0xffffffffu, send, 16);
                v[i] = (up ? v[i + 8] : v[i]) + recv;
            }
        }
        {
            const bool up = (lane & 8) != 0;
#pragma unroll
            for (int i = 0; i < 4; i++) {
                const float send = up ? v[i] : v[i + 4];
                const float recv = __shfl_xor_sync(0xffffffffu, send, 8);
                v[i] = (up ? v[i + 4] : v[i]) + recv;
            }
        }
        {
            const bool up = (lane & 4) != 0;
#pragma unroll
            for (int i = 0; i < 2; i++) {
                const float send = up ? v[i] : v[i + 2];
                const float recv = __shfl_xor_sync(0xffffffffu, send, 4);
                v[i] = (up ? v[i + 2] : v[i]) + recv;
            }
        }
        {
            const bool up = (lane & 2) != 0;
            const float send = up ? v[0] : v[1];
            const float recv = __shfl_xor_sync(0xffffffffu, send, 2);
            v[0] = (up ? v[1] : v[0]) + recv;
        }
        v[0] += __shfl_xor_sync(0xffffffffu, v[0], 1);

        const int vrow = (lane >> 1) & 15;
        if ((lane & 1) == 0) s_part[t & 1][vrow][w] = v[0];
        __syncthreads();   // the ONLY CTA barrier per step

        // ---- finalize (warps 0 and 2, lanes<16) ----
        if (lane < ROWS_PER_CTA && (w == 0 || w == 2)) {
            float d0 = 0.0f, d1 = 0.0f, d2 = 0.0f, d3 = 0.0f;
#pragma unroll
            for (int j = 0; j < 4; j++) {
                d0 += s_part[t & 1][lane][j];
                d1 += s_part[t & 1][lane][j + 4];
                d2 += s_part[t & 1][lane][j + 8];
                d3 += s_part[t & 1][lane][j + 12];
            }
            const float dot = (d0 + d1) + (d2 + d3);
            const float nh = (1.0f - LEAK) * hid + LEAK * (u + dot);
            const float na = tanhf(nh);
            hid = nh;
            if (w == 0 && t < T_STEPS - 1) {
                // critical path: publish line + release tag = B_{t&1} + t + 1
                g_lines[t & 1][cta].act[lane] = na;
                __syncwarp(0x0000ffffu);
                if (lane == 0)
                    st_release_u32(&g_lines[t & 1][cta].tag,
                                   ((t & 1) ? B1 : B0) + (unsigned int)(t + 1));
            } else if (w == 2) {
                // off critical path: result tensors
                out_act[(size_t)t * HIDDEN + fin_row] = na;
                out_hid[(size_t)t * HIDDEN + fin_row] = nh;
            }
        }
        // Safety chains:
        //  - s_part[t&1] rewritten at t+2 only after all warps passed bar@t+1,
        //    which warps 0/2 reach only after their step-t reads.
        //  - line parity p rewritten at t+2 only after every CTA observed tag
        //    t+1 from everyone, which required their step-t reads to finish.
    }
}

// ---------------- launch ----------------
extern "C" void kernel_launch(void* const* d_in, const int* in_sizes, int n_in,
                              void* d_out, int out_size) {
    const float* input = (const float*)d_in[0];   // [T, IN_DIM]
    const float* w_ih  = (const float*)d_in[1];   // [H, IN_DIM]
    const float* b_ih  = (const float*)d_in[2];   // [H]
    const float* w_hh  = (const float*)d_in[3];   // [H, H]

    float* out_act = (float*)d_out;                            // [T, H]
    float* out_hid = (float*)d_out + (size_t)T_STEPS * HIDDEN; // [T, H]

    inp_proj_kernel<<<T_STEPS / 16, 256>>>(input, w_ih, b_ih);
    reservoir_kernel<<<NCTA, TPB>>>(w_hh, out_act, out_hid);
}

// round 10
// speedup vs baseline: 1.5133x; 1.5133x over previous
#include <cuda_runtime.h>
#include <cstdint>
#include <cstddef>

#define T_STEPS 4096
#define IN_DIM  128
#define HIDDEN  2048
#define LEAK    0.9f
#define NCTA    128
#define TPB     512
#define ROWS_PER_CTA 16   // HIDDEN / NCTA

// ---------------- device scratch (static: no allocations allowed) ----------------
__device__ float g_inp[(size_t)T_STEPS * HIDDEN];    // precomputed input projection [T,H]
__device__ float g_actbuf[2][HIDDEN];                // QUIET act double buffer (no polls ever)
__device__ __align__(512) unsigned int g_slot[NCTA]; // packed arrival slots (write-only + 1 sweeper)
__device__ __align__(128) unsigned int g_sense[32];  // sense word on its own line

// ---------------- packed fp32x2 helpers ----------------
__device__ __forceinline__ unsigned long long pack2(float lo, float hi) {
    unsigned long long u;
    asm("mov.b64 %0, {%1, %2};" : "=l"(u) : "f"(lo), "f"(hi));
    return u;
}
__device__ __forceinline__ void unpack2(unsigned long long u, float& lo, float& hi) {
    asm("mov.b64 {%0, %1}, %2;" : "=f"(lo), "=f"(hi) : "l"(u));
}
__device__ __forceinline__ unsigned long long ffma2(unsigned long long a,
                                                    unsigned long long b,
                                                    unsigned long long c) {
    unsigned long long d;
    asm("fma.rn.f32x2 %0, %1, %2, %3;" : "=l"(d) : "l"(a), "l"(b), "l"(c));
    return d;
}

// ---------------- sync primitives (stores + weak polls only) ----------------
__device__ __forceinline__ void st_release_u32(unsigned int* p, unsigned int v) {
    asm volatile("st.release.gpu.global.u32 [%0], %1;" :: "l"(p), "r"(v) : "memory");
}
__device__ __forceinline__ unsigned int ld_poll_u32(const unsigned int* p) {
    unsigned int v;
    asm volatile("ld.volatile.global.u32 %0, [%1];" : "=r"(v) : "l"(p) : "memory");
    return v;
}
__device__ __forceinline__ void ld_poll_v4(const unsigned int* p,
                                           unsigned int& a, unsigned int& b,
                                           unsigned int& c, unsigned int& d) {
    asm volatile("ld.volatile.global.v4.u32 {%0,%1,%2,%3}, [%4];"
                 : "=r"(a), "=r"(b), "=r"(c), "=r"(d) : "l"(p) : "memory");
}
// Watchdog-friendly backoff: engages only after spins >= threshold.
__device__ __forceinline__ void poll_backoff(unsigned int& spins) {
    if (++spins >= 1024u) { __nanosleep(64); }
}

// ---------------- reset: zero slots + sense (stream-ordered, replay-safe) ----------------
__global__ void reset_kernel() {
    const int i = threadIdx.x;
    if (i < NCTA) g_slot[i] = 0u;
    if (i == NCTA) g_sense[0] = 0u;
}

// ---------------- phase A: inp_proj[t][h] = input[t,:] . w_ih[h,:] + b_ih[h] ----------------
__global__ void inp_proj_kernel(const float* __restrict__ input,
                                const float* __restrict__ w_ih,
                                const float* __restrict__ b_ih) {
    __shared__ float s_in[16 * IN_DIM];
    const int tblk = blockIdx.x;
    const int tid  = threadIdx.x;

    for (int i = tid; i < 16 * IN_DIM; i += 256)
        s_in[i] = input[(size_t)tblk * 16 * IN_DIM + i];
    __syncthreads();

    const float4* s_in4 = reinterpret_cast<const float4*>(s_in);

    for (int j = 0; j < 8; j++) {
        const int h = tid + 256 * j;
        float acc[16];
        const float b = b_ih[h];
#pragma unroll
        for (int t = 0; t < 16; t++) acc[t] = b;

        const float4* wrow = reinterpret_cast<const float4*>(w_ih + (size_t)h * IN_DIM);
#pragma unroll 4
        for (int kc = 0; kc < IN_DIM / 4; kc++) {
            const float4 w4 = wrow[kc];
#pragma unroll
            for (int t = 0; t < 16; t++) {
                const float4 iv = s_in4[t * (IN_DIM / 4) + kc];  // warp-broadcast
                acc[t] += w4.x * iv.x + w4.y * iv.y + w4.z * iv.z + w4.w * iv.w;
            }
        }
#pragma unroll
        for (int t = 0; t < 16; t++)
            g_inp[(size_t)(tblk * 16 + t) * HIDDEN + h] = acc[t];
    }
}

// ---------------- phase B: persistent recurrence kernel ----------------
// 128 CTAs x 512 threads. CTA b owns rows [16b, 16b+16); thread tid owns all
// 16 rows x cols [4*tid, 4*tid+4) (64 weights in regs).
// Sync pipeline (all store-based; act data + sense lines stay quiet):
//   arrive : w0 lane0 of each CTA st.release g_slot[cta] = t+1 after finalize
//   gather : CTA0 warp15 weak-sweeps the 128 packed slots, st.release sense=t+1
//   release: tid0 of each CTA weak-polls sense >= t; __syncthreads; __ldcg acts
__global__ void __launch_bounds__(TPB, 1)
reservoir_kernel(const float* __restrict__ w_hh,
                 float* __restrict__ out_act,
                 float* __restrict__ out_hid) {
    __shared__ float s_part[2][ROWS_PER_CTA][17];   // parity double-buffered

    const int tid  = threadIdx.x;
    const int lane = tid & 31;
    const int w    = tid >> 5;                   // warp id 0..15
    const int cta  = blockIdx.x;
    const int base_row = cta * ROWS_PER_CTA;
    const bool is_agg = (cta == 0) && (w == 15); // aggregator warp

    // Load weights: W[r] = cols [4*tid, 4*tid+4) of row base_row + r.
    unsigned long long W[ROWS_PER_CTA][2];
#pragma unroll
    for (int r = 0; r < ROWS_PER_CTA; r++) {
        const float4 wv = reinterpret_cast<const float4*>(
            w_hh + (size_t)(base_row + r) * HIDDEN)[tid];
        W[r][0] = pack2(wv.x, wv.y);
        W[r][1] = pack2(wv.z, wv.w);
    }

    const int fin_row = base_row + lane;   // finalize row (lanes<16 of warps 0,2)
    float hid = 0.0f;                      // identical copies in warps 0 and 2

    // ---- t = 0 peeled: previous act is zero -> dot = 0; arrive slot = 1 ----
    if (lane < ROWS_PER_CTA && (w == 0 || w == 2)) {
        const float u0 = g_inp[fin_row];
        const float nh = LEAK * u0;
        const float na = tanhf(nh);
        hid = nh;
        if (w == 0) {
            g_actbuf[0][fin_row] = na;          // step 0 -> parity 0
            __syncwarp(0x0000ffffu);
            if (lane == 0) st_release_u32(&g_slot[cta], 1u);
        } else {
            out_act[fin_row] = na;
            out_hid[fin_row] = nh;
        }
    }
    // aggregator: gather step-0 arrivals, publish sense = 1
    if (is_agg) {
        unsigned int spins = 0u;
        bool ok;
        do {
            unsigned int s0, s1, s2, s3;
            ld_poll_v4(g_slot + 4 * lane, s0, s1, s2, s3);
            ok = (s0 >= 1u) & (s1 >= 1u) & (s2 >= 1u) & (s3 >= 1u);
            if (!ok) poll_backoff(spins);
        } while (!__all_sync(0xffffffffu, ok));
        if (lane == 0) st_release_u32(&g_sense[0], 1u);
    }

    for (int t = 1; t < T_STEPS; t++) {
        // prefetch u_t (warps 0 and 2 only; issued before the wait)
        float u = 0.0f;
        if (lane < ROWS_PER_CTA && (w == 0 || w == 2))
            u = g_inp[(size_t)t * HIDDEN + fin_row];

        // ---- single poller per CTA on the quiet sense line ----
        if (tid == 0) {
            unsigned int spins = 0u;
            unsigned int sv = ld_poll_u32(&g_sense[0]);
            while (sv < (unsigned int)t) {
                poll_backoff(spins);
                sv = ld_poll_u32(&g_sense[0]);
            }
        }
        __syncthreads();   // (A) act_{t-1} visible everywhere

        // act slice straight into registers (L2-coherent; quiet buffer)
        const float4 a = __ldcg(
            reinterpret_cast<const float4*>(g_actbuf[(t + 1) & 1]) + tid);
        const unsigned long long A0 = pack2(a.x, a.y);
        const unsigned long long A1 = pack2(a.z, a.w);

        // ---- 16 independent 2-deep FFMA2 chains ----
        float v[ROWS_PER_CTA];
#pragma unroll
        for (int r = 0; r < ROWS_PER_CTA; r++) {
            unsigned long long P = ffma2(W[r][0], A0, 0ull);
            P = ffma2(W[r][1], A1, P);
            float lo, hi; unpack2(P, lo, hi);
            v[r] = lo + hi;
        }

        // ---- value-splitting warp butterfly: 16 values -> 1 per lane ----
        {
            const bool up = (lane & 16) != 0;
#pragma unroll
            for (int i = 0; i < 8; i++) {
                const float send = up ? v[i] : v[i + 8];
                const float recv = __shfl_xor_sync(0xffffffffu, send, 16);
                v[i] = (up ? v[i + 8] : v[i]) + recv;
            }
        }
        {
            const bool up = (lane & 8) != 0;
#pragma unroll
            for (int i = 0; i < 4; i++) {
                const float send = up ? v[i] : v[i + 4];
                const float recv = __shfl_xor_sync(0xffffffffu, send, 8);
                v[i] = (up ? v[i + 4] : v[i]) + recv;
            }
        }
        {
            const bool up = (lane & 4) != 0;
#pragma unroll
            for (int i = 0; i < 2; i++) {
                const float send = up ? v[i] : v[i + 2];
                const float recv = __shfl_xor_sync(0xffffffffu, send, 4);
                v[i] = (up ? v[i + 2] : v[i]) + recv;
            }
        }
        {
            const bool up = (lane & 2) != 0;
            const float send = up ? v[0] : v[1];
            const float recv = __shfl_xor_sync(0xffffffffu, send, 2);
            v[0] = (up ? v[1] : v[0]) + recv;
        }
        v[0] += __shfl_xor_sync(0xffffffffu, v[0], 1);

        const int vrow = (lane >> 1) & 15;
        if ((lane & 1) == 0) s_part[t & 1][vrow][w] = v[0];
        __syncthreads();   // (B) s_part ready

        // ---- finalize (warps 0 and 2, lanes<16) ----
        if (lane < ROWS_PER_CTA && (w == 0 || w == 2)) {
            float d0 = 0.0f, d1 = 0.0f, d2 = 0.0f, d3 = 0.0f;
#pragma unroll
            for (int j = 0; j < 4; j++) {
                d0 += s_part[t & 1][lane][j];
                d1 += s_part[t & 1][lane][j + 4];
                d2 += s_part[t & 1][lane][j + 8];
                d3 += s_part[t & 1][lane][j + 12];
            }
            const float dot = (d0 + d1) + (d2 + d3);
            const float nh = (1.0f - LEAK) * hid + LEAK * (u + dot);
            const float na = tanhf(nh);
            hid = nh;
            if (w == 0) {
                if (t < T_STEPS - 1) {
                    // critical path: publish act (quiet buffer) + arrive
                    g_actbuf[t & 1][fin_row] = na;
                    __syncwarp(0x0000ffffu);
                    if (lane == 0)
                        st_release_u32(&g_slot[cta], (unsigned int)(t + 1));
                }
            } else {
                // off critical path: result tensors
                out_act[(size_t)t * HIDDEN + fin_row] = na;
                out_hid[(size_t)t * HIDDEN + fin_row] = nh;
            }
        }

        // ---- aggregator: gather step-t arrivals, publish sense = t+1 ----
        if (is_agg && t < T_STEPS - 1) {
            const unsigned int s = (unsigned int)(t + 1);
            unsigned int spins = 0u;
            bool ok;
            do {
                unsigned int s0, s1, s2, s3;
                ld_poll_v4(g_slot + 4 * lane, s0, s1, s2, s3);
                ok = (s0 >= s) & (s1 >= s) & (s2 >= s) & (s3 >= s);
                if (!ok) poll_backoff(spins);
            } while (!__all_sync(0xffffffffu, ok));
            if (lane == 0) st_release_u32(&g_sense[0], s);
        }
        // Safety: s_part[t&1] rewritten at t+2 only after bar(A)@t+2, which
        // needs sense t+2 -> all slots t+2 -> every CTA finished step-t+1
        // reads (and hence step-t reads). g_actbuf parity overwrite: same chain.
    }
}

// ---------------- launch ----------------
extern "C" void kernel_launch(void* const* d_in, const int* in_sizes, int n_in,
                              void* d_out, int out_size) {
    const float* input = (const float*)d_in[0];   // [T, IN_DIM]
    const float* w_ih  = (const float*)d_in[1];   // [H, IN_DIM]
    const float* b_ih  = (const float*)d_in[2];   // [H]
    const float* w_hh  = (const float*)d_in[3];   // [H, H]

    float* out_act = (float*)d_out;                            // [T, H]
    float* out_hid = (float*)d_out + (size_t)T_STEPS * HIDDEN; // [T, H]

    reset_kernel<<<1, 256>>>();
    inp_proj_kernel<<<T_STEPS / 16, 256>>>(input, w_ih, b_ih);
    reservoir_kernel<<<NCTA, TPB>>>(w_hh, out_act, out_hid);
}

// round 14
// speedup vs baseline: 2.1191x; 1.4003x over previous
#include <cuda_runtime.h>
#include <cstdint>
#include <cstddef>

#define T_STEPS 4096
#define IN_DIM  128
#define HIDDEN  2048
#define LEAK    0.9f
#define NCTA    128
#define TPB     512
#define ROWS_PER_CTA 16   // HIDDEN / NCTA

// ---------------- device scratch (static: no allocations allowed) ----------------
__device__ float g_inp[(size_t)T_STEPS * HIDDEN];   // precomputed input projection [T,H]
__device__ float g_actbuf[2][HIDDEN];               // QUIET act double buffer
__device__ unsigned long long g_count;              // barrier counter (reset each launch)

// ---------------- packed fp32x2 helpers ----------------
__device__ __forceinline__ unsigned long long pack2(float lo, float hi) {
    unsigned long long u;
    asm("mov.b64 %0, {%1, %2};" : "=l"(u) : "f"(lo), "f"(hi));
    return u;
}
__device__ __forceinline__ void unpack2(unsigned long long u, float& lo, float& hi) {
    asm("mov.b64 {%0, %1}, %2;" : "=f"(lo), "=f"(hi) : "l"(u));
}
__device__ __forceinline__ unsigned long long ffma2(unsigned long long a,
                                                    unsigned long long b,
                                                    unsigned long long c) {
    unsigned long long d;
    asm("fma.rn.f32x2 %0, %1, %2, %3;" : "=l"(d) : "l"(a), "l"(b), "l"(c));
    return d;
}

// ---------------- barrier primitives (CG-style one-thread arrive/poll) ----------------
__device__ __forceinline__ void arrive_release(unsigned long long* p) {
    unsigned long long old;
    asm volatile("atom.add.release.gpu.global.u64 %0, [%1], 1;"
                 : "=l"(old) : "l"(p) : "memory");
}
__device__ __forceinline__ unsigned long long ld_acquire_u64(const unsigned long long* p) {
    unsigned long long v;
    asm volatile("ld.acquire.gpu.global.u64 %0, [%1];" : "=l"(v) : "l"(p) : "memory");
    return v;
}
__device__ __forceinline__ void poll_backoff(unsigned int& spins) {
    if (++spins >= 2048u) { __nanosleep(64); }
}

// ---------------- reset: zero the counter (stream-ordered, replay-safe) ----------------
__global__ void reset_kernel() {
    g_count = 0ull;
}

// ---------------- phase A: inp_proj[t][h] = input[t,:] . w_ih[h,:] + b_ih[h] ----------------
__global__ void inp_proj_kernel(const float* __restrict__ input,
                                const float* __restrict__ w_ih,
                                const float* __restrict__ b_ih) {
    __shared__ float s_in[16 * IN_DIM];
    const int tblk = blockIdx.x;
    const int tid  = threadIdx.x;

    for (int i = tid; i < 16 * IN_DIM; i += 256)
        s_in[i] = input[(size_t)tblk * 16 * IN_DIM + i];
    __syncthreads();

    const float4* s_in4 = reinterpret_cast<const float4*>(s_in);

    for (int j = 0; j < 8; j++) {
        const int h = tid + 256 * j;
        float acc[16];
        const float b = b_ih[h];
#pragma unroll
        for (int t = 0; t < 16; t++) acc[t] = b;

        const float4* wrow = reinterpret_cast<const float4*>(w_ih + (size_t)h * IN_DIM);
#pragma unroll 4
        for (int kc = 0; kc < IN_DIM / 4; kc++) {
            const float4 w4 = wrow[kc];
#pragma unroll
            for (int t = 0; t < 16; t++) {
                const float4 iv = s_in4[t * (IN_DIM / 4) + kc];  // warp-broadcast
                acc[t] += w4.x * iv.x + w4.y * iv.y + w4.z * iv.z + w4.w * iv.w;
            }
        }
#pragma unroll
        for (int t = 0; t < 16; t++)
            g_inp[(size_t)(tblk * 16 + t) * HIDDEN + h] = acc[t];
    }
}

// Gather 16 lane values (lanes 0..15) into 4 uint4 on every lane<16 (lane 0 stores).
__device__ __forceinline__ void gather16(float na, uint4 q[4]) {
#pragma unroll
    for (int k = 0; k < 4; k++) {
        q[k].x = __float_as_uint(__shfl_sync(0x0000ffffu, na, 4 * k + 0));
        q[k].y = __float_as_uint(__shfl_sync(0x0000ffffu, na, 4 * k + 1));
        q[k].z = __float_as_uint(__shfl_sync(0x0000ffffu, na, 4 * k + 2));
        q[k].w = __float_as_uint(__shfl_sync(0x0000ffffu, na, 4 * k + 3));
    }
}

// ---------------- phase B: persistent recurrence kernel ----------------
// 128 CTAs x 512 threads. CTA b owns rows [16b, 16b+16); thread tid owns all
// 16 rows x cols [4*tid, 4*tid+4) (64 weights in regs).
// Barrier (proven-fast topology): ONE counter line. Arrive: warp0 lane0
// publishes the CTA's 16 acts itself (4x STG.128 after shfl gather) then
// atom.add.release (orders its own stores). Discover: tid0 ld.acquire-polls
// count >= 128*t; __syncthreads releases the CTA (CG grid.sync pattern).
__global__ void __launch_bounds__(TPB, 1)
reservoir_kernel(const float* __restrict__ w_hh,
                 float* __restrict__ out_act,
                 float* __restrict__ out_hid) {
    __shared__ float s_part[2][ROWS_PER_CTA][17];   // parity double-buffered

    const int tid  = threadIdx.x;
    const int lane = tid & 31;
    const int w    = tid >> 5;                   // warp id 0..15
    const int cta  = blockIdx.x;
    const int base_row = cta * ROWS_PER_CTA;

    // Load weights: W[r] = cols [4*tid, 4*tid+4) of row base_row + r.
    unsigned long long W[ROWS_PER_CTA][2];
#pragma unroll
    for (int r = 0; r < ROWS_PER_CTA; r++) {
        const float4 wv = reinterpret_cast<const float4*>(
            w_hh + (size_t)(base_row + r) * HIDDEN)[tid];
        W[r][0] = pack2(wv.x, wv.y);
        W[r][1] = pack2(wv.z, wv.w);
    }

    const int fin_row = base_row + lane;   // finalize row (lanes<16 of warps 0,2)
    float hid = 0.0f;                      // identical copies in warps 0 and 2

    // ---- t = 0 peeled: previous act is zero -> dot = 0; publish + arrive ----
    if (lane < ROWS_PER_CTA && (w == 0 || w == 2)) {
        const float u0 = g_inp[fin_row];
        const float nh = LEAK * u0;
        const float na = tanhf(nh);
        hid = nh;
        if (w == 0) {
            uint4 q[4];
            gather16(na, q);
            if (lane == 0) {
                uint4* dst = reinterpret_cast<uint4*>(&g_actbuf[0][base_row]);
#pragma unroll
                for (int k = 0; k < 4; k++) dst[k] = q[k];
                arrive_release(&g_count);          // orders lane0's own stores
            }
        } else {
            out_act[fin_row] = na;
            out_hid[fin_row] = nh;
        }
    }

    for (int t = 1; t < T_STEPS; t++) {
        // prefetch u_t (warps 0 and 2 only; issued before the wait)
        float u = 0.0f;
        if (lane < ROWS_PER_CTA && (w == 0 || w == 2))
            u = g_inp[(size_t)t * HIDDEN + fin_row];

        // ---- discover: tid0 acquire-polls the single counter ----
        if (tid == 0) {
            const unsigned long long target = (unsigned long long)NCTA * (unsigned long long)t;
            unsigned int spins = 0u;
            while (ld_acquire_u64(&g_count) < target) poll_backoff(spins);
        }
        __syncthreads();   // (A) act_{t-1} visible to the whole CTA

        // act slice straight into registers (quiet buffer, L2-coherent)
        const float4 a = __ldcg(
            reinterpret_cast<const float4*>(g_actbuf[(t + 1) & 1]) + tid);
        const unsigned long long A0 = pack2(a.x, a.y);
        const unsigned long long A1 = pack2(a.z, a.w);

        // ---- 16 independent 2-deep FFMA2 chains ----
        float v[ROWS_PER_CTA];
#pragma unroll
        for (int r = 0; r < ROWS_PER_CTA; r++) {
            unsigned long long P = ffma2(W[r][0], A0, 0ull);
            P = ffma2(W[r][1], A1, P);
            float lo, hi; unpack2(P, lo, hi);
            v[r] = lo + hi;
        }

        // ---- value-splitting warp butterfly: 16 values -> 1 per lane ----
        {
            const bool up = (lane & 16) != 0;
#pragma unroll
            for (int i = 0; i < 8; i++) {
                const float send = up ? v[i] : v[i + 8];
                const float recv = __shfl_xor_sync(0xffffffffu, send, 16);
                v[i] = (up ? v[i + 8] : v[i]) + recv;
            }
        }
        {
            const bool up = (lane & 8) != 0;
#pragma unroll
            for (int i = 0; i < 4; i++) {
                const float send = up ? v[i] : v[i + 4];
                const float recv = __shfl_xor_sync(0xffffffffu, send, 8);
                v[i] = (up ? v[i + 4] : v[i]) + recv;
            }
        }
        {
            const bool up = (lane & 4) != 0;
#pragma unroll
            for (int i = 0; i < 2; i++) {
                const float send = up ? v[i] : v[i + 2];
                const float recv = __shfl_xor_sync(0xffffffffu, send, 4);
                v[i] = (up ? v[i + 2] : v[i]) + recv;
            }
        }
        {
            const bool up = (lane & 2) != 0;
            const float send = up ? v[0] : v[1];
            const float recv = __shfl_xor_sync(0xffffffffu, send, 2);
            v[0] = (up ? v[1] : v[0]) + recv;
        }
        v[0] += __shfl_xor_sync(0xffffffffu, v[0], 1);

        const int vrow = (lane >> 1) & 15;
        if ((lane & 1) == 0) s_part[t & 1][vrow][w] = v[0];
        __syncthreads();   // (B) s_part ready

        // ---- finalize (warps 0 and 2, lanes<16) ----
        if (lane < ROWS_PER_CTA && (w == 0 || w == 2)) {
            float d0 = 0.0f, d1 = 0.0f, d2 = 0.0f, d3 = 0.0f;
#pragma unroll
            for (int j = 0; j < 4; j++) {
                d0 += s_part[t & 1][lane][j];
                d1 += s_part[t & 1][lane][j + 4];
                d2 += s_part[t & 1][lane][j + 8];
                d3 += s_part[t & 1][lane][j + 12];
            }
            const float dot = (d0 + d1) + (d2 + d3);
            const float nh = (1.0f - LEAK) * hid + LEAK * (u + dot);
            const float na = tanhf(nh);
            hid = nh;
            if (w == 0) {
                if (t < T_STEPS - 1) {
                    // critical path: single-thread publish + release-arrive
                    uint4 q[4];
                    gather16(na, q);
                    if (lane == 0) {
                        uint4* dst = reinterpret_cast<uint4*>(&g_actbuf[t & 1][base_row]);
#pragma unroll
                        for (int k = 0; k < 4; k++) dst[k] = q[k];
                        arrive_release(&g_count);
                    }
                }
            } else {
                // off critical path: result tensors
                out_act[(size_t)t * HIDDEN + fin_row] = na;
                out_hid[(size_t)t * HIDDEN + fin_row] = nh;
            }
        }
        // Safety:
        //  - step t writes parity t&1, reads parity (t+1)&1 (disjoint).
        //  - overwrite of parity t&1 at step t is gated by poll(count>=128t),
        //    i.e. all CTAs arrived for t-1, which postdates their completed
        //    reads of parity t&1 at step t-1.
        //  - s_part[t&1] rewritten at t+2 only after bar(A)@t+2 > bar(B)@t+1.
        //  - counter reset each launch; targets are absolute -> replay-safe.
    }
}

// ---------------- launch ----------------
extern "C" void kernel_launch(void* const* d_in, const int* in_sizes, int n_in,
                              void* d_out, int out_size) {
    const float* input = (const float*)d_in[0];   // [T, IN_DIM]
    const float* w_ih  = (const float*)d_in[1];   // [H, IN_DIM]
    const float* b_ih  = (const float*)d_in[2];   // [H]
    const float* w_hh  = (const float*)d_in[3];   // [H, H]

    float* out_act = (float*)d_out;                            // [T, H]
    float* out_hid = (float*)d_out + (size_t)T_STEPS * HIDDEN; // [T, H]

    reset_kernel<<<1, 1>>>();
    inp_proj_kernel<<<T_STEPS / 16, 256>>>(input, w_ih, b_ih);
    reservoir_kernel<<<NCTA, TPB>>>(w_hh, out_act, out_hid);
}